// round 1
// baseline (speedup 1.0000x reference)
#include <cuda_runtime.h>
#include <cuda_bf16.h>

// Problem constants
#define B_  2
#define S_  2048
#define D_  1024
#define H_  8
#define E_  128
#define KW_ 16
#define M_  (B_ * S_)        // 4096 tokens
#define N1_ (3 * H_ * E_)    // 3072 fused qkv output cols
#define K_  D_               // 1024 reduction dim

// Scratch (static device memory; no allocations allowed)
__device__ float g_Wpack[D_ * N1_];            // [d][proj*1024 + h*128 + e]  ~12.6 MB
__device__ float g_q[B_ * H_ * S_ * E_];       // [b][h][s][e] 16.8 MB
__device__ float g_k[B_ * H_ * S_ * E_];
__device__ float g_v[B_ * H_ * S_ * E_];
__device__ float g_attn[B_ * S_ * H_ * E_];    // [b][s][h][e] 16.8 MB

// ---------------------------------------------------------------------------
// Pack Wq/Wk/Wv ([H,D,E] each) into contiguous [K=D, N=3*H*E] row-major.
// ---------------------------------------------------------------------------
__global__ void pack_w_kernel(const float* __restrict__ Wq,
                              const float* __restrict__ Wk,
                              const float* __restrict__ Wv) {
    int t = blockIdx.x * blockDim.x + threadIdx.x;
    int total = D_ * N1_;
    if (t >= total) return;
    int d = t / N1_;
    int n = t - d * N1_;
    int proj = n >> 10;          // 0,1,2
    int h    = (n >> 7) & 7;
    int e    = n & 127;
    const float* W = (proj == 0) ? Wq : (proj == 1) ? Wk : Wv;
    g_Wpack[t] = W[(h * D_ + d) * E_ + e];
}

// ---------------------------------------------------------------------------
// Fused QKV SGEMM: C[m=(b,s)][n=(proj,h,e)] = x @ Wpack + bias
// 128x128 block tile, BK=8, 256 threads, 8x8 per-thread microtile.
// Epilogue scatters into g_q/g_k/g_v with layout [B,H,S,E].
// Each 128-col block tile lies entirely within one (proj, head).
// ---------------------------------------------------------------------------
__global__ __launch_bounds__(256, 2) void gemm_qkv_kernel(
    const float* __restrict__ x,
    const float* __restrict__ bq,
    const float* __restrict__ bk,
    const float* __restrict__ bv) {
    __shared__ float As[8][128];
    __shared__ float Bs[8][128];

    const int bm = blockIdx.y * 128;
    const int bn = blockIdx.x * 128;
    const int tid = threadIdx.x;

    // A tile load mapping: 128 rows x 8 cols, float4 per thread
    const int arow = tid >> 1;          // 0..127
    const int acol = (tid & 1) * 4;     // 0 or 4
    // B tile load mapping: 8 rows x 128 cols, float4 per thread
    const int brow = tid >> 5;          // 0..7
    const int bcol = (tid & 31) * 4;    // 0..124

    const int tm = (tid >> 4) * 8;      // 0..120
    const int tn = (tid & 15) * 8;      // 0..120

    float acc[8][8];
#pragma unroll
    for (int i = 0; i < 8; i++)
#pragma unroll
        for (int j = 0; j < 8; j++) acc[i][j] = 0.f;

    for (int k0 = 0; k0 < K_; k0 += 8) {
        float4 a4 = *(const float4*)(x + (size_t)(bm + arow) * K_ + k0 + acol);
        As[acol + 0][arow] = a4.x;
        As[acol + 1][arow] = a4.y;
        As[acol + 2][arow] = a4.z;
        As[acol + 3][arow] = a4.w;
        *(float4*)&Bs[brow][bcol] =
            *(const float4*)(g_Wpack + (size_t)(k0 + brow) * N1_ + bn + bcol);
        __syncthreads();

#pragma unroll
        for (int kk = 0; kk < 8; kk++) {
            float4 a0 = *(const float4*)&As[kk][tm];
            float4 a1 = *(const float4*)&As[kk][tm + 4];
            float4 b0 = *(const float4*)&Bs[kk][tn];
            float4 b1 = *(const float4*)&Bs[kk][tn + 4];
            float ra[8] = {a0.x, a0.y, a0.z, a0.w, a1.x, a1.y, a1.z, a1.w};
            float rb[8] = {b0.x, b0.y, b0.z, b0.w, b1.x, b1.y, b1.z, b1.w};
#pragma unroll
            for (int i = 0; i < 8; i++)
#pragma unroll
                for (int j = 0; j < 8; j++) acc[i][j] += ra[i] * rb[j];
        }
        __syncthreads();
    }

    // Epilogue: this block's column range sits in one (proj, head)
    const int proj = bn >> 10;
    const int h    = (bn >> 7) & 7;
    const float* bias = (proj == 0) ? bq : (proj == 1) ? bk : bv;
    float* dstbase    = (proj == 0) ? g_q : (proj == 1) ? g_k : g_v;
    const int e0 = (bn & 127) + tn;     // == tn (bn multiple of 128)

    float4 bia0 = *(const float4*)(bias + h * E_ + e0);
    float4 bia1 = *(const float4*)(bias + h * E_ + e0 + 4);

#pragma unroll
    for (int i = 0; i < 8; i++) {
        int m = bm + tm + i;
        int b = m >> 11;        // S_ = 2048
        int s = m & (S_ - 1);
        float* dst = dstbase + ((size_t)(b * H_ + h) * S_ + s) * E_ + e0;
        float4 v0 = {acc[i][0] + bia0.x, acc[i][1] + bia0.y,
                     acc[i][2] + bia0.z, acc[i][3] + bia0.w};
        float4 v1 = {acc[i][4] + bia1.x, acc[i][5] + bia1.y,
                     acc[i][6] + bia1.z, acc[i][7] + bia1.w};
        *(float4*)dst = v0;
        *(float4*)(dst + 4) = v1;
    }
}

// ---------------------------------------------------------------------------
// Dilated local attention: one warp per (b,h,s) token.
// Lane l owns e in [4l, 4l+4). Padded positions use the bias vector and are
// INCLUDED in the softmax (matches reference where(valid, k, bias)).
// Output scaled by 1/sqrt(E) AFTER softmax*value (faithful quirk).
// Writes g_attn with layout [B,S,H,E] so the output GEMM reads it row-major.
// ---------------------------------------------------------------------------
__global__ __launch_bounds__(256) void attn_kernel(
    const float* __restrict__ bk,
    const float* __restrict__ bv,
    const int*   __restrict__ dilations) {
    const int warp = (blockIdx.x * blockDim.x + threadIdx.x) >> 5;
    const int lane = threadIdx.x & 31;
    // warp -> (b, h, s); s fastest for k/v L2 locality
    const int s  = warp & (S_ - 1);
    const int bh = warp >> 11;
    const int h  = bh & (H_ - 1);
    const int b  = bh >> 3;

    const int d   = dilations[h];
    const int off = (d * (KW_ - 1)) >> 1;

    const float* qp    = g_q + ((size_t)(b * H_ + h) * S_ + s) * E_;
    const float* kbase = g_k + (size_t)(b * H_ + h) * S_ * E_;
    const float* vbase = g_v + (size_t)(b * H_ + h) * S_ * E_;

    const float4 qv = *(const float4*)(qp + lane * 4);
    const float4 kbias = *(const float4*)(bk + h * E_ + lane * 4);
    const float4 vbias = *(const float4*)(bv + h * E_ + lane * 4);

    float logits[KW_];
#pragma unroll
    for (int j = 0; j < KW_; j++) {
        int pos = s + d * j - off;
        bool valid = (pos >= 0) && (pos < S_);
        float4 kv = valid ? *(const float4*)(kbase + (size_t)pos * E_ + lane * 4)
                          : kbias;
        float p = qv.x * kv.x + qv.y * kv.y + qv.z * kv.z + qv.w * kv.w;
        p += __shfl_xor_sync(0xFFFFFFFFu, p, 16);
        p += __shfl_xor_sync(0xFFFFFFFFu, p, 8);
        p += __shfl_xor_sync(0xFFFFFFFFu, p, 4);
        p += __shfl_xor_sync(0xFFFFFFFFu, p, 2);
        p += __shfl_xor_sync(0xFFFFFFFFu, p, 1);
        logits[j] = p;
    }

    float mx = logits[0];
#pragma unroll
    for (int j = 1; j < KW_; j++) mx = fmaxf(mx, logits[j]);
    float ssum = 0.f;
    float w[KW_];
#pragma unroll
    for (int j = 0; j < KW_; j++) {
        w[j] = __expf(logits[j] - mx);
        ssum += w[j];
    }
    const float scale = (1.0f / ssum) * 0.08838834764831845f;  // 1/sqrt(128)

    float4 acc = {0.f, 0.f, 0.f, 0.f};
#pragma unroll
    for (int j = 0; j < KW_; j++) {
        int pos = s + d * j - off;
        bool valid = (pos >= 0) && (pos < S_);
        float4 vv = valid ? *(const float4*)(vbase + (size_t)pos * E_ + lane * 4)
                          : vbias;
        float wj = w[j] * scale;
        acc.x += wj * vv.x;
        acc.y += wj * vv.y;
        acc.z += wj * vv.z;
        acc.w += wj * vv.w;
    }

    float* out = g_attn + ((size_t)(b * S_ + s) * H_ + h) * E_ + lane * 4;
    *(float4*)out = acc;
}

// ---------------------------------------------------------------------------
// Output projection SGEMM: out[m=(b,s)][d] = g_attn[m][:] @ Wo[(h,e)][d] + bo
// Wo is [H,E,D] row-major == [K=1024, N=1024] row-major: no packing needed.
// ---------------------------------------------------------------------------
__global__ __launch_bounds__(256, 2) void gemm_out_kernel(
    const float* __restrict__ Wo,
    const float* __restrict__ bo,
    float* __restrict__ out) {
    __shared__ float As[8][128];
    __shared__ float Bs[8][128];

    const int bm = blockIdx.y * 128;
    const int bn = blockIdx.x * 128;
    const int tid = threadIdx.x;

    const int arow = tid >> 1;
    const int acol = (tid & 1) * 4;
    const int brow = tid >> 5;
    const int bcol = (tid & 31) * 4;
    const int tm = (tid >> 4) * 8;
    const int tn = (tid & 15) * 8;

    float acc[8][8];
#pragma unroll
    for (int i = 0; i < 8; i++)
#pragma unroll
        for (int j = 0; j < 8; j++) acc[i][j] = 0.f;

    for (int k0 = 0; k0 < K_; k0 += 8) {
        float4 a4 = *(const float4*)(g_attn + (size_t)(bm + arow) * K_ + k0 + acol);
        As[acol + 0][arow] = a4.x;
        As[acol + 1][arow] = a4.y;
        As[acol + 2][arow] = a4.z;
        As[acol + 3][arow] = a4.w;
        *(float4*)&Bs[brow][bcol] =
            *(const float4*)(Wo + (size_t)(k0 + brow) * D_ + bn + bcol);
        __syncthreads();

#pragma unroll
        for (int kk = 0; kk < 8; kk++) {
            float4 a0 = *(const float4*)&As[kk][tm];
            float4 a1 = *(const float4*)&As[kk][tm + 4];
            float4 b0 = *(const float4*)&Bs[kk][tn];
            float4 b1 = *(const float4*)&Bs[kk][tn + 4];
            float ra[8] = {a0.x, a0.y, a0.z, a0.w, a1.x, a1.y, a1.z, a1.w};
            float rb[8] = {b0.x, b0.y, b0.z, b0.w, b1.x, b1.y, b1.z, b1.w};
#pragma unroll
            for (int i = 0; i < 8; i++)
#pragma unroll
                for (int j = 0; j < 8; j++) acc[i][j] += ra[i] * rb[j];
        }
        __syncthreads();
    }

    float4 bia0 = *(const float4*)(bo + bn + tn);
    float4 bia1 = *(const float4*)(bo + bn + tn + 4);
#pragma unroll
    for (int i = 0; i < 8; i++) {
        int m = bm + tm + i;
        float* dst = out + (size_t)m * D_ + bn + tn;
        float4 v0 = {acc[i][0] + bia0.x, acc[i][1] + bia0.y,
                     acc[i][2] + bia0.z, acc[i][3] + bia0.w};
        float4 v1 = {acc[i][4] + bia1.x, acc[i][5] + bia1.y,
                     acc[i][6] + bia1.z, acc[i][7] + bia1.w};
        *(float4*)dst = v0;
        *(float4*)(dst + 4) = v1;
    }
}

// ---------------------------------------------------------------------------
// Launch
// Inputs: x, Wq, bq, Wk, bk, Wv, bv, Wo, bo, dilations
// ---------------------------------------------------------------------------
extern "C" void kernel_launch(void* const* d_in, const int* in_sizes, int n_in,
                              void* d_out, int out_size) {
    const float* x   = (const float*)d_in[0];
    const float* Wq  = (const float*)d_in[1];
    const float* bq  = (const float*)d_in[2];
    const float* Wk  = (const float*)d_in[3];
    const float* bk  = (const float*)d_in[4];
    const float* Wv  = (const float*)d_in[5];
    const float* bv  = (const float*)d_in[6];
    const float* Wo  = (const float*)d_in[7];
    const float* bo  = (const float*)d_in[8];
    const int*   dil = (const int*)d_in[9];
    float* out = (float*)d_out;

    // 1) pack weights
    {
        int total = D_ * N1_;
        pack_w_kernel<<<(total + 255) / 256, 256>>>(Wq, Wk, Wv);
    }
    // 2) fused qkv projection
    {
        dim3 grid(N1_ / 128, M_ / 128);  // (24, 32)
        gemm_qkv_kernel<<<grid, 256>>>(x, bq, bk, bv);
    }
    // 3) windowed attention (one warp per token)
    {
        int warps = B_ * H_ * S_;        // 32768
        attn_kernel<<<warps / 8, 256>>>(bk, bv, dil);
    }
    // 4) output projection
    {
        dim3 grid(D_ / 128, M_ / 128);   // (8, 32)
        gemm_out_kernel<<<grid, 256>>>(Wo, bo, out);
    }
}

// round 11
// speedup vs baseline: 1.0072x; 1.0072x over previous
#include <cuda_runtime.h>
#include <cuda_bf16.h>
#include <cstdint>

// Problem constants
#define B_  2
#define S_  2048
#define D_  1024
#define H_  8
#define E_  128
#define KW_ 16
#define M_  (B_ * S_)        // 4096 tokens
#define N1_ (3 * H_ * E_)    // 3072 fused qkv output cols
#define K_  D_               // 1024 reduction dim

// Scratch (static device memory)
__device__ float g_Wpack[D_ * N1_];            // [d][proj*1024 + h*128 + e]
__device__ float g_q[B_ * H_ * S_ * E_];       // [b][h][s][e]
__device__ float g_k[B_ * H_ * S_ * E_];
__device__ float g_v[B_ * H_ * S_ * E_];
__device__ float g_attn[B_ * S_ * H_ * E_];    // [b][s][h][e]

// ---------------------------------------------------------------------------
// f32x2 packed FMA helpers (sm_100+ PTX; SASS FFMA2 on B300)
// ---------------------------------------------------------------------------
typedef unsigned long long u64b;

__device__ __forceinline__ void fma2(u64b& c, u64b a, u64b b) {
    asm("fma.rn.f32x2 %0, %1, %2, %0;" : "+l"(c) : "l"(a), "l"(b));
}
__device__ __forceinline__ u64b pack2(float lo, float hi) {
    u64b r;
    asm("mov.b64 %0, {%1, %2};" : "=l"(r) : "f"(lo), "f"(hi));
    return r;
}
__device__ __forceinline__ float2 unpack2(u64b v) {
    float2 f;
    asm("mov.b64 {%0, %1}, %2;" : "=f"(f.x), "=f"(f.y) : "l"(v));
    return f;
}

// ---------------------------------------------------------------------------
// Pack Wq/Wk/Wv ([H,D,E] each) into contiguous [K=D, N=3*H*E] row-major.
// (round-1 verbatim)
// ---------------------------------------------------------------------------
__global__ void pack_w_kernel(const float* __restrict__ Wq,
                              const float* __restrict__ Wk,
                              const float* __restrict__ Wv) {
    int t = blockIdx.x * blockDim.x + threadIdx.x;
    int total = D_ * N1_;
    if (t >= total) return;
    int d = t / N1_;
    int n = t - d * N1_;
    int proj = n >> 10;
    int h    = (n >> 7) & 7;
    int e    = n & 127;
    const float* W = (proj == 0) ? Wq : (proj == 1) ? Wk : Wv;
    g_Wpack[t] = W[(h * D_ + d) * E_ + e];
}

// ---------------------------------------------------------------------------
// Fused QKV SGEMM with f32x2 packed math. Round-1 structure:
// 128x128 tile, BK=8, 256 threads, 8x8 per-thread microtile.
// Adds: register double-buffered global loads, packed accumulators.
// ---------------------------------------------------------------------------
__global__ __launch_bounds__(256, 2) void gemm_qkv_kernel(
    const float* __restrict__ x,
    const float* __restrict__ bq,
    const float* __restrict__ bk,
    const float* __restrict__ bv) {
    __shared__ float As[8][128];
    __shared__ float Bs[8][128];

    const int bm = blockIdx.y * 128;
    const int bn = blockIdx.x * 128;
    const int tid = threadIdx.x;

    const int arow = tid >> 1;          // 0..127
    const int acol = (tid & 1) * 4;     // 0 or 4
    const int brow = tid >> 5;          // 0..7
    const int bcol = (tid & 31) * 4;    // 0..124

    const int tm = (tid >> 4) * 8;      // 0..120
    const int tn = (tid & 15) * 8;      // 0..120

    u64b acc2[8][4];
#pragma unroll
    for (int i = 0; i < 8; i++)
#pragma unroll
        for (int j = 0; j < 4; j++) acc2[i][j] = 0ull;

    const float* aptr = x + (size_t)(bm + arow) * K_ + acol;
    const float* bptr = g_Wpack + (size_t)brow * N1_ + bn + bcol;

    float4 a_nxt = *(const float4*)aptr;
    float4 b_nxt = *(const float4*)bptr;

    for (int k0 = 0; k0 < K_; k0 += 8) {
        As[acol + 0][arow] = a_nxt.x;
        As[acol + 1][arow] = a_nxt.y;
        As[acol + 2][arow] = a_nxt.z;
        As[acol + 3][arow] = a_nxt.w;
        *(float4*)&Bs[brow][bcol] = b_nxt;
        __syncthreads();

        if (k0 + 8 < K_) {
            a_nxt = *(const float4*)(aptr + k0 + 8);
            b_nxt = *(const float4*)(bptr + (size_t)(k0 + 8) * N1_);
        }

#pragma unroll
        for (int kk = 0; kk < 8; kk++) {
            float4 a0 = *(const float4*)&As[kk][tm];
            float4 a1 = *(const float4*)&As[kk][tm + 4];
            u64b bb0 = *(const u64b*)&Bs[kk][tn];
            u64b bb1 = *(const u64b*)&Bs[kk][tn + 2];
            u64b bb2 = *(const u64b*)&Bs[kk][tn + 4];
            u64b bb3 = *(const u64b*)&Bs[kk][tn + 6];
            float ra[8] = {a0.x, a0.y, a0.z, a0.w, a1.x, a1.y, a1.z, a1.w};
#pragma unroll
            for (int i = 0; i < 8; i++) {
                u64b aa = pack2(ra[i], ra[i]);
                fma2(acc2[i][0], aa, bb0);
                fma2(acc2[i][1], aa, bb1);
                fma2(acc2[i][2], aa, bb2);
                fma2(acc2[i][3], aa, bb3);
            }
        }
        __syncthreads();
    }

    // Epilogue: this block's column range sits in one (proj, head)
    const int proj = bn >> 10;
    const int h    = (bn >> 7) & 7;
    const float* bias = (proj == 0) ? bq : (proj == 1) ? bk : bv;
    float* dstbase    = (proj == 0) ? g_q : (proj == 1) ? g_k : g_v;
    const int e0 = tn;

    float4 bia0 = *(const float4*)(bias + h * E_ + e0);
    float4 bia1 = *(const float4*)(bias + h * E_ + e0 + 4);

#pragma unroll
    for (int i = 0; i < 8; i++) {
        int m = bm + tm + i;
        int b = m >> 11;
        int s = m & (S_ - 1);
        float* dst = dstbase + ((size_t)(b * H_ + h) * S_ + s) * E_ + e0;
        float2 p0 = unpack2(acc2[i][0]);
        float2 p1 = unpack2(acc2[i][1]);
        float2 p2 = unpack2(acc2[i][2]);
        float2 p3 = unpack2(acc2[i][3]);
        float4 v0 = {p0.x + bia0.x, p0.y + bia0.y, p1.x + bia0.z, p1.y + bia0.w};
        float4 v1 = {p2.x + bia1.x, p2.y + bia1.y, p3.x + bia1.z, p3.y + bia1.w};
        *(float4*)dst = v0;
        *(float4*)(dst + 4) = v1;
    }
}

// ---------------------------------------------------------------------------
// Dilated local attention (round-1 verbatim; passing)
// ---------------------------------------------------------------------------
__global__ __launch_bounds__(256) void attn_kernel(
    const float* __restrict__ bk,
    const float* __restrict__ bv,
    const int*   __restrict__ dilations) {
    const int warp = (blockIdx.x * blockDim.x + threadIdx.x) >> 5;
    const int lane = threadIdx.x & 31;
    const int s  = warp & (S_ - 1);
    const int bh = warp >> 11;
    const int h  = bh & (H_ - 1);
    const int b  = bh >> 3;

    const int d   = dilations[h];
    const int off = (d * (KW_ - 1)) >> 1;

    const float* qp    = g_q + ((size_t)(b * H_ + h) * S_ + s) * E_;
    const float* kbase = g_k + (size_t)(b * H_ + h) * S_ * E_;
    const float* vbase = g_v + (size_t)(b * H_ + h) * S_ * E_;

    const float4 qv    = *(const float4*)(qp + lane * 4);
    const float4 kbias = *(const float4*)(bk + h * E_ + lane * 4);
    const float4 vbias = *(const float4*)(bv + h * E_ + lane * 4);

    float logits[KW_];
#pragma unroll
    for (int j = 0; j < KW_; j++) {
        int pos = s + d * j - off;
        bool valid = (pos >= 0) && (pos < S_);
        float4 kv = valid ? *(const float4*)(kbase + (size_t)pos * E_ + lane * 4)
                          : kbias;
        float p = qv.x * kv.x + qv.y * kv.y + qv.z * kv.z + qv.w * kv.w;
        p += __shfl_xor_sync(0xFFFFFFFFu, p, 16);
        p += __shfl_xor_sync(0xFFFFFFFFu, p, 8);
        p += __shfl_xor_sync(0xFFFFFFFFu, p, 4);
        p += __shfl_xor_sync(0xFFFFFFFFu, p, 2);
        p += __shfl_xor_sync(0xFFFFFFFFu, p, 1);
        logits[j] = p;
    }

    float mx = logits[0];
#pragma unroll
    for (int j = 1; j < KW_; j++) mx = fmaxf(mx, logits[j]);
    float ssum = 0.f;
    float w[KW_];
#pragma unroll
    for (int j = 0; j < KW_; j++) {
        w[j] = __expf(logits[j] - mx);
        ssum += w[j];
    }
    const float scale = (1.0f / ssum) * 0.08838834764831845f;  // 1/sqrt(128)

    float4 acc = {0.f, 0.f, 0.f, 0.f};
#pragma unroll
    for (int j = 0; j < KW_; j++) {
        int pos = s + d * j - off;
        bool valid = (pos >= 0) && (pos < S_);
        float4 vv = valid ? *(const float4*)(vbase + (size_t)pos * E_ + lane * 4)
                          : vbias;
        float wj = w[j] * scale;
        acc.x += wj * vv.x;
        acc.y += wj * vv.y;
        acc.z += wj * vv.z;
        acc.w += wj * vv.w;
    }

    float* out = g_attn + ((size_t)(b * S_ + s) * H_ + h) * E_ + lane * 4;
    *(float4*)out = acc;
}

// ---------------------------------------------------------------------------
// Output projection SGEMM with f32x2 packed math (round-1 structure)
// ---------------------------------------------------------------------------
__global__ __launch_bounds__(256, 2) void gemm_out_kernel(
    const float* __restrict__ Wo,
    const float* __restrict__ bo,
    float* __restrict__ out) {
    __shared__ float As[8][128];
    __shared__ float Bs[8][128];

    const int bm = blockIdx.y * 128;
    const int bn = blockIdx.x * 128;
    const int tid = threadIdx.x;

    const int arow = tid >> 1;
    const int acol = (tid & 1) * 4;
    const int brow = tid >> 5;
    const int bcol = (tid & 31) * 4;
    const int tm = (tid >> 4) * 8;
    const int tn = (tid & 15) * 8;

    u64b acc2[8][4];
#pragma unroll
    for (int i = 0; i < 8; i++)
#pragma unroll
        for (int j = 0; j < 4; j++) acc2[i][j] = 0ull;

    const float* aptr = g_attn + (size_t)(bm + arow) * K_ + acol;
    const float* bptr = Wo + (size_t)brow * D_ + bn + bcol;

    float4 a_nxt = *(const float4*)aptr;
    float4 b_nxt = *(const float4*)bptr;

    for (int k0 = 0; k0 < K_; k0 += 8) {
        As[acol + 0][arow] = a_nxt.x;
        As[acol + 1][arow] = a_nxt.y;
        As[acol + 2][arow] = a_nxt.z;
        As[acol + 3][arow] = a_nxt.w;
        *(float4*)&Bs[brow][bcol] = b_nxt;
        __syncthreads();

        if (k0 + 8 < K_) {
            a_nxt = *(const float4*)(aptr + k0 + 8);
            b_nxt = *(const float4*)(bptr + (size_t)(k0 + 8) * D_);
        }

#pragma unroll
        for (int kk = 0; kk < 8; kk++) {
            float4 a0 = *(const float4*)&As[kk][tm];
            float4 a1 = *(const float4*)&As[kk][tm + 4];
            u64b bb0 = *(const u64b*)&Bs[kk][tn];
            u64b bb1 = *(const u64b*)&Bs[kk][tn + 2];
            u64b bb2 = *(const u64b*)&Bs[kk][tn + 4];
            u64b bb3 = *(const u64b*)&Bs[kk][tn + 6];
            float ra[8] = {a0.x, a0.y, a0.z, a0.w, a1.x, a1.y, a1.z, a1.w};
#pragma unroll
            for (int i = 0; i < 8; i++) {
                u64b aa = pack2(ra[i], ra[i]);
                fma2(acc2[i][0], aa, bb0);
                fma2(acc2[i][1], aa, bb1);
                fma2(acc2[i][2], aa, bb2);
                fma2(acc2[i][3], aa, bb3);
            }
        }
        __syncthreads();
    }

    float4 bia0 = *(const float4*)(bo + bn + tn);
    float4 bia1 = *(const float4*)(bo + bn + tn + 4);
#pragma unroll
    for (int i = 0; i < 8; i++) {
        int m = bm + tm + i;
        float* dst = out + (size_t)m * D_ + bn + tn;
        float2 p0 = unpack2(acc2[i][0]);
        float2 p1 = unpack2(acc2[i][1]);
        float2 p2 = unpack2(acc2[i][2]);
        float2 p3 = unpack2(acc2[i][3]);
        float4 v0 = {p0.x + bia0.x, p0.y + bia0.y, p1.x + bia0.z, p1.y + bia0.w};
        float4 v1 = {p2.x + bia1.x, p2.y + bia1.y, p3.x + bia1.z, p3.y + bia1.w};
        *(float4*)dst = v0;
        *(float4*)(dst + 4) = v1;
    }
}

// ---------------------------------------------------------------------------
// Launch — inputs: x, Wq, bq, Wk, bk, Wv, bv, Wo, bo, dilations
// ---------------------------------------------------------------------------
extern "C" void kernel_launch(void* const* d_in, const int* in_sizes, int n_in,
                              void* d_out, int out_size) {
    const float* x   = (const float*)d_in[0];
    const float* Wq  = (const float*)d_in[1];
    const float* bq  = (const float*)d_in[2];
    const float* Wk  = (const float*)d_in[3];
    const float* bk  = (const float*)d_in[4];
    const float* Wv  = (const float*)d_in[5];
    const float* bv  = (const float*)d_in[6];
    const float* Wo  = (const float*)d_in[7];
    const float* bo  = (const float*)d_in[8];
    const int*   dil = (const int*)d_in[9];
    float* out = (float*)d_out;

    // 1) pack weights
    {
        int total = D_ * N1_;
        pack_w_kernel<<<(total + 255) / 256, 256>>>(Wq, Wk, Wv);
    }
    // 2) fused qkv projection (f32x2)
    {
        dim3 grid(N1_ / 128, M_ / 128);  // (24, 32)
        gemm_qkv_kernel<<<grid, 256>>>(x, bq, bk, bv);
    }
    // 3) windowed attention
    {
        int warps = B_ * H_ * S_;        // 32768
        attn_kernel<<<warps / 8, 256>>>(bk, bv, dil);
    }
    // 4) output projection (f32x2)
    {
        dim3 grid(D_ / 128, M_ / 128);   // (8, 32)
        gemm_out_kernel<<<grid, 256>>>(Wo, bo, out);
    }
}

// round 15
// speedup vs baseline: 1.1796x; 1.1712x over previous
#include <cuda_runtime.h>
#include <cuda_bf16.h>
#include <cstdint>

// Problem constants
#define B_  2
#define S_  2048
#define D_  1024
#define H_  8
#define E_  128
#define KW_ 16
#define M_  (B_ * S_)        // 4096 tokens
#define N1_ (3 * H_ * E_)    // 3072 fused qkv output cols
#define K_  D_               // 1024 reduction dim

// Scratch (static device memory)
__device__ float g_Wpack[D_ * N1_];            // [d][proj*1024 + h*128 + e]
__device__ float g_q[B_ * H_ * S_ * E_];       // [b][h][s][e]
__device__ float g_k[B_ * H_ * S_ * E_];
__device__ float g_v[B_ * H_ * S_ * E_];
__device__ float g_attn[B_ * S_ * H_ * E_];    // [b][s][h][e]

// ---------------------------------------------------------------------------
// f32x2 packed FMA helpers (validated round 11)
// ---------------------------------------------------------------------------
typedef unsigned long long u64b;

__device__ __forceinline__ void fma2(u64b& c, u64b a, u64b b) {
    asm("fma.rn.f32x2 %0, %1, %2, %0;" : "+l"(c) : "l"(a), "l"(b));
}
__device__ __forceinline__ u64b pack2(float lo, float hi) {
    u64b r;
    asm("mov.b64 %0, {%1, %2};" : "=l"(r) : "f"(lo), "f"(hi));
    return r;
}
__device__ __forceinline__ float2 unpack2(u64b v) {
    float2 f;
    asm("mov.b64 {%0, %1}, %2;" : "=f"(f.x), "=f"(f.y) : "l"(v));
    return f;
}

// ---------------------------------------------------------------------------
// Pack Wq/Wk/Wv ([H,D,E] each) into contiguous [K=D, N=3*H*E] row-major.
// ---------------------------------------------------------------------------
__global__ void pack_w_kernel(const float* __restrict__ Wq,
                              const float* __restrict__ Wk,
                              const float* __restrict__ Wv) {
    int t = blockIdx.x * blockDim.x + threadIdx.x;
    int total = D_ * N1_;
    if (t >= total) return;
    int d = t / N1_;
    int n = t - d * N1_;
    int proj = n >> 10;
    int h    = (n >> 7) & 7;
    int e    = n & 127;
    const float* W = (proj == 0) ? Wq : (proj == 1) ? Wk : Wv;
    g_Wpack[t] = W[(h * D_ + d) * E_ + e];
}

// ---------------------------------------------------------------------------
// SGEMM core: 128x128 CTA tile, BK=8, 256 threads, 8x8 thread tile.
// Thread columns = {4t..4t+3} U {64+4t..64+4t+3} (contiguous float4 groups)
//   -> conflict-free B LDS (single crossbar phase per LDS.64).
// 2-stage smem double buffer (16KB), 1 syncthreads per k-tile.
// ---------------------------------------------------------------------------
#define GEMM_CORE(APTR, BPTR, LDB)                                              \
    __shared__ float As[2][8][128];                                             \
    __shared__ float Bs[2][8][128];                                             \
    const int tid = threadIdx.x;                                                \
    const int bm = blockIdx.y * 128;                                            \
    const int bn = blockIdx.x * 128;                                            \
    const int arow = tid >> 1;            /* 0..127 */                          \
    const int acol = (tid & 1) * 4;       /* 0 or 4 */                          \
    const int brow = tid >> 5;            /* 0..7   */                          \
    const int bcol = (tid & 31) * 4;      /* 0..124 */                          \
    const int tm = (tid >> 4) * 8;        /* rows tm..tm+7 */                   \
    const int tc = (tid & 15) * 4;        /* cols tc..tc+3 and 64+tc..+3 */     \
    u64b acc2[8][4];                                                            \
    _Pragma("unroll")                                                           \
    for (int i = 0; i < 8; i++)                                                 \
        _Pragma("unroll")                                                       \
        for (int j = 0; j < 4; j++) acc2[i][j] = 0ull;                          \
    const float* aptr = (APTR) + (size_t)(bm + arow) * K_ + acol;               \
    const float* bptr = (BPTR) + (size_t)brow * (LDB) + bn + bcol;              \
    float4 a_nxt = *(const float4*)aptr;                                        \
    float4 b_nxt = *(const float4*)bptr;                                        \
    As[0][acol + 0][arow] = a_nxt.x;                                            \
    As[0][acol + 1][arow] = a_nxt.y;                                            \
    As[0][acol + 2][arow] = a_nxt.z;                                            \
    As[0][acol + 3][arow] = a_nxt.w;                                            \
    *(float4*)&Bs[0][brow][bcol] = b_nxt;                                       \
    __syncthreads();                                                            \
    _Pragma("unroll 1")                                                         \
    for (int k0 = 0; k0 < K_; k0 += 8) {                                        \
        const int buf = (k0 >> 3) & 1;                                          \
        if (k0 + 8 < K_) {                                                      \
            a_nxt = *(const float4*)(aptr + k0 + 8);                            \
            b_nxt = *(const float4*)(bptr + (size_t)(k0 + 8) * (LDB));          \
        }                                                                       \
        _Pragma("unroll")                                                       \
        for (int kk = 0; kk < 8; kk++) {                                        \
            float4 a0 = *(const float4*)&As[buf][kk][tm];                       \
            float4 a1 = *(const float4*)&As[buf][kk][tm + 4];                   \
            u64b bb0 = *(const u64b*)&Bs[buf][kk][tc];                          \
            u64b bb1 = *(const u64b*)&Bs[buf][kk][tc + 2];                      \
            u64b bb2 = *(const u64b*)&Bs[buf][kk][tc + 64];                     \
            u64b bb3 = *(const u64b*)&Bs[buf][kk][tc + 66];                     \
            float ra[8] = {a0.x, a0.y, a0.z, a0.w, a1.x, a1.y, a1.z, a1.w};     \
            _Pragma("unroll")                                                   \
            for (int i = 0; i < 8; i++) {                                       \
                u64b aa = pack2(ra[i], ra[i]);                                  \
                fma2(acc2[i][0], aa, bb0);                                      \
                fma2(acc2[i][1], aa, bb1);                                      \
                fma2(acc2[i][2], aa, bb2);                                      \
                fma2(acc2[i][3], aa, bb3);                                      \
            }                                                                   \
        }                                                                       \
        if (k0 + 8 < K_) {                                                      \
            const int nb = buf ^ 1;                                             \
            As[nb][acol + 0][arow] = a_nxt.x;                                   \
            As[nb][acol + 1][arow] = a_nxt.y;                                   \
            As[nb][acol + 2][arow] = a_nxt.z;                                   \
            As[nb][acol + 3][arow] = a_nxt.w;                                   \
            *(float4*)&Bs[nb][brow][bcol] = b_nxt;                              \
        }                                                                       \
        __syncthreads();                                                        \
    }

// ---------------------------------------------------------------------------
// Fused QKV SGEMM: epilogue scatters q/k/v + bias into [b,h,s,e]
// ---------------------------------------------------------------------------
__global__ __launch_bounds__(256, 2) void gemm_qkv_kernel(
    const float* __restrict__ x,
    const float* __restrict__ bq,
    const float* __restrict__ bk,
    const float* __restrict__ bv) {
    GEMM_CORE(x, g_Wpack, N1_)

    const int proj = bn >> 10;
    const int h    = (bn >> 7) & 7;
    const float* bias = ((proj == 0) ? bq : (proj == 1) ? bk : bv) + h * E_;
    float* dstbase    = (proj == 0) ? g_q : (proj == 1) ? g_k : g_v;

    float4 bia0 = *(const float4*)(bias + tc);
    float4 bia1 = *(const float4*)(bias + tc + 64);

#pragma unroll
    for (int i = 0; i < 8; i++) {
        int m = bm + tm + i;
        int b = m >> 11;
        int s = m & (S_ - 1);
        float* row = dstbase + ((size_t)(b * H_ + h) * S_ + s) * E_;
        float2 p0 = unpack2(acc2[i][0]);
        float2 p1 = unpack2(acc2[i][1]);
        float2 p2 = unpack2(acc2[i][2]);
        float2 p3 = unpack2(acc2[i][3]);
        float4 v0 = {p0.x + bia0.x, p0.y + bia0.y, p1.x + bia0.z, p1.y + bia0.w};
        float4 v1 = {p2.x + bia1.x, p2.y + bia1.y, p3.x + bia1.z, p3.y + bia1.w};
        *(float4*)(row + tc) = v0;
        *(float4*)(row + tc + 64) = v1;
    }
}

// ---------------------------------------------------------------------------
// Output projection SGEMM: out + bo
// ---------------------------------------------------------------------------
__global__ __launch_bounds__(256, 2) void gemm_out_kernel(
    const float* __restrict__ Wo,
    const float* __restrict__ bo,
    float* __restrict__ out) {
    GEMM_CORE(g_attn, Wo, D_)

    float4 bia0 = *(const float4*)(bo + bn + tc);
    float4 bia1 = *(const float4*)(bo + bn + tc + 64);

#pragma unroll
    for (int i = 0; i < 8; i++) {
        int m = bm + tm + i;
        float* row = out + (size_t)m * D_ + bn;
        float2 p0 = unpack2(acc2[i][0]);
        float2 p1 = unpack2(acc2[i][1]);
        float2 p2 = unpack2(acc2[i][2]);
        float2 p3 = unpack2(acc2[i][3]);
        float4 v0 = {p0.x + bia0.x, p0.y + bia0.y, p1.x + bia0.z, p1.y + bia0.w};
        float4 v1 = {p2.x + bia1.x, p2.y + bia1.y, p3.x + bia1.z, p3.y + bia1.w};
        *(float4*)(row + tc) = v0;
        *(float4*)(row + tc + 64) = v1;
    }
}

// ---------------------------------------------------------------------------
// Dilated local attention (round-1 verbatim; passing)
// ---------------------------------------------------------------------------
__global__ __launch_bounds__(256) void attn_kernel(
    const float* __restrict__ bk,
    const float* __restrict__ bv,
    const int*   __restrict__ dilations) {
    const int warp = (blockIdx.x * blockDim.x + threadIdx.x) >> 5;
    const int lane = threadIdx.x & 31;
    const int s  = warp & (S_ - 1);
    const int bh = warp >> 11;
    const int h  = bh & (H_ - 1);
    const int b  = bh >> 3;

    const int d   = dilations[h];
    const int off = (d * (KW_ - 1)) >> 1;

    const float* qp    = g_q + ((size_t)(b * H_ + h) * S_ + s) * E_;
    const float* kbase = g_k + (size_t)(b * H_ + h) * S_ * E_;
    const float* vbase = g_v + (size_t)(b * H_ + h) * S_ * E_;

    const float4 qv    = *(const float4*)(qp + lane * 4);
    const float4 kbias = *(const float4*)(bk + h * E_ + lane * 4);
    const float4 vbias = *(const float4*)(bv + h * E_ + lane * 4);

    float logits[KW_];
#pragma unroll
    for (int j = 0; j < KW_; j++) {
        int pos = s + d * j - off;
        bool valid = (pos >= 0) && (pos < S_);
        float4 kv = valid ? *(const float4*)(kbase + (size_t)pos * E_ + lane * 4)
                          : kbias;
        float p = qv.x * kv.x + qv.y * kv.y + qv.z * kv.z + qv.w * kv.w;
        p += __shfl_xor_sync(0xFFFFFFFFu, p, 16);
        p += __shfl_xor_sync(0xFFFFFFFFu, p, 8);
        p += __shfl_xor_sync(0xFFFFFFFFu, p, 4);
        p += __shfl_xor_sync(0xFFFFFFFFu, p, 2);
        p += __shfl_xor_sync(0xFFFFFFFFu, p, 1);
        logits[j] = p;
    }

    float mx = logits[0];
#pragma unroll
    for (int j = 1; j < KW_; j++) mx = fmaxf(mx, logits[j]);
    float ssum = 0.f;
    float w[KW_];
#pragma unroll
    for (int j = 0; j < KW_; j++) {
        w[j] = __expf(logits[j] - mx);
        ssum += w[j];
    }
    const float scale = (1.0f / ssum) * 0.08838834764831845f;  // 1/sqrt(128)

    float4 acc = {0.f, 0.f, 0.f, 0.f};
#pragma unroll
    for (int j = 0; j < KW_; j++) {
        int pos = s + d * j - off;
        bool valid = (pos >= 0) && (pos < S_);
        float4 vv = valid ? *(const float4*)(vbase + (size_t)pos * E_ + lane * 4)
                          : vbias;
        float wj = w[j] * scale;
        acc.x += wj * vv.x;
        acc.y += wj * vv.y;
        acc.z += wj * vv.z;
        acc.w += wj * vv.w;
    }

    float* outp = g_attn + ((size_t)(b * S_ + s) * H_ + h) * E_ + lane * 4;
    *(float4*)outp = acc;
}

// ---------------------------------------------------------------------------
// Launch — inputs: x, Wq, bq, Wk, bk, Wv, bv, Wo, bo, dilations
// ---------------------------------------------------------------------------
extern "C" void kernel_launch(void* const* d_in, const int* in_sizes, int n_in,
                              void* d_out, int out_size) {
    const float* x   = (const float*)d_in[0];
    const float* Wq  = (const float*)d_in[1];
    const float* bq  = (const float*)d_in[2];
    const float* Wk  = (const float*)d_in[3];
    const float* bk  = (const float*)d_in[4];
    const float* Wv  = (const float*)d_in[5];
    const float* bv  = (const float*)d_in[6];
    const float* Wo  = (const float*)d_in[7];
    const float* bo  = (const float*)d_in[8];
    const int*   dil = (const int*)d_in[9];
    float* out = (float*)d_out;

    // 1) pack weights
    {
        int total = D_ * N1_;
        pack_w_kernel<<<(total + 255) / 256, 256>>>(Wq, Wk, Wv);
    }
    // 2) fused qkv projection
    {
        dim3 grid(N1_ / 128, M_ / 128);  // (24, 32)
        gemm_qkv_kernel<<<grid, 256>>>(x, bq, bk, bv);
    }
    // 3) windowed attention
    {
        int warps = B_ * H_ * S_;        // 32768
        attn_kernel<<<warps / 8, 256>>>(bk, bv, dil);
    }
    // 4) output projection
    {
        dim3 grid(D_ / 128, M_ / 128);   // (8, 32)
        gemm_out_kernel<<<grid, 256>>>(Wo, bo, out);
    }
}